// round 5
// baseline (speedup 1.0000x reference)
#include <cuda_runtime.h>
#include <cuda_fp16.h>
#include <cuda_bf16.h>

// Problem constants (fixed by the dataset)
#define HID    32
#define NIRR   16
#define OUTC   32
#define FANIN  (HID * NIRR)      // 512
#define MAX_ATOMS 50000
#define MAX_EDGES 800000

// Scratch: A[a][i*32+c] = sum_h nf[a][h] * W[(h*16+i)*32+c], stored fp16.
// Row = 512 halves = 1024 B = 8 x 128B lines. Line l holds irreps 2l, 2l+1.
__device__ __half g_Ah[(size_t)MAX_ATOMS * FANIN];

// Counting-sort scratch
__device__ int    g_count[MAX_ATOMS];
__device__ int    g_offset[MAX_ATOMS];
__device__ int    g_nvalid;
__device__ float4 g_rec4[MAX_EDGES];    // {ex, ey, ez, bitcast(src)}
__device__ int    g_rectgt[MAX_EDGES];

// ---------------------------------------------------------------------------
// Kernel 0: out[t, c] = b[c]   (float4 vectorized)
// ---------------------------------------------------------------------------
__global__ void init_out_kernel(float4* __restrict__ out4,
                                const float4* __restrict__ b4, int n4) {
    int t = blockIdx.x * blockDim.x + threadIdx.x;
    if (t < n4) out4[t] = __ldg(&b4[t & 7]);
}

// ---------------------------------------------------------------------------
// Kernel 1: A = NF @ W'   (M=50000, K=32, N=512), output fp16.
// ---------------------------------------------------------------------------
__global__ void __launch_bounds__(256, 4)
precompute_A_kernel(const float* __restrict__ nf,
                    const float* __restrict__ W, int n_atoms) {
    const int tid = threadIdx.x;
    const int n0 = tid * 2;
    const int n1 = n0 + 1;

    float w0[HID], w1[HID];
#pragma unroll
    for (int h = 0; h < HID; h++) {
        w0[h] = __ldg(&W[(h * NIRR + (n0 >> 5)) * OUTC + (n0 & 31)]);
        w1[h] = __ldg(&W[(h * NIRR + (n1 >> 5)) * OUTC + (n1 & 31)]);
    }

    __shared__ float snf[4 * HID];

    for (int a0 = blockIdx.x * 4; a0 < n_atoms; a0 += gridDim.x * 4) {
        __syncthreads();
        if (tid < 4 * HID) {
            int a = a0 + (tid >> 5);
            snf[tid] = (a < n_atoms) ? nf[(size_t)a * HID + (tid & 31)] : 0.0f;
        }
        __syncthreads();

        float acc00 = 0.f, acc01 = 0.f, acc10 = 0.f, acc11 = 0.f;
        float acc20 = 0.f, acc21 = 0.f, acc30 = 0.f, acc31 = 0.f;
#pragma unroll
        for (int h = 0; h < HID; h++) {
            float f0 = snf[0 * HID + h];
            float f1 = snf[1 * HID + h];
            float f2 = snf[2 * HID + h];
            float f3 = snf[3 * HID + h];
            acc00 = fmaf(f0, w0[h], acc00); acc01 = fmaf(f0, w1[h], acc01);
            acc10 = fmaf(f1, w0[h], acc10); acc11 = fmaf(f1, w1[h], acc11);
            acc20 = fmaf(f2, w0[h], acc20); acc21 = fmaf(f2, w1[h], acc21);
            acc30 = fmaf(f3, w0[h], acc30); acc31 = fmaf(f3, w1[h], acc31);
        }
        if (a0 + 0 < n_atoms)
            *(__half2*)&g_Ah[(size_t)(a0 + 0) * FANIN + n0] = __floats2half2_rn(acc00, acc01);
        if (a0 + 1 < n_atoms)
            *(__half2*)&g_Ah[(size_t)(a0 + 1) * FANIN + n0] = __floats2half2_rn(acc10, acc11);
        if (a0 + 2 < n_atoms)
            *(__half2*)&g_Ah[(size_t)(a0 + 2) * FANIN + n0] = __floats2half2_rn(acc20, acc21);
        if (a0 + 3 < n_atoms)
            *(__half2*)&g_Ah[(size_t)(a0 + 3) * FANIN + n0] = __floats2half2_rn(acc30, acc31);
    }
}

// ---------------------------------------------------------------------------
// Sort step 1: zero counters
// ---------------------------------------------------------------------------
__global__ void zero_count_kernel(int n_atoms) {
    int i = blockIdx.x * blockDim.x + threadIdx.x;
    if (i < n_atoms) g_count[i] = 0;
}

// ---------------------------------------------------------------------------
// Sort step 2: histogram over edge sources
// ---------------------------------------------------------------------------
__global__ void hist_kernel(const int* __restrict__ eidx,
                            int n_edges, int n_atoms) {
    int e = blockIdx.x * blockDim.x + threadIdx.x;
    if (e >= n_edges) return;
    int src = eidx[e];
    int tgt = eidx[n_edges + e];
    if ((unsigned)src < (unsigned)n_atoms && (unsigned)tgt < (unsigned)n_atoms)
        atomicAdd(&g_count[src], 1);
}

// ---------------------------------------------------------------------------
// Sort step 3: exclusive scan of g_count -> g_offset (single block, 1024 thr)
// ---------------------------------------------------------------------------
__global__ void __launch_bounds__(1024, 1)
scan_kernel(int n_atoms) {
    __shared__ int warp_off[32];
    __shared__ int carry_s;
    const int tid  = threadIdx.x;
    const int lane = tid & 31;
    const int wid  = tid >> 5;
    if (tid == 0) carry_s = 0;
    __syncthreads();

    for (int base = 0; base < n_atoms; base += 1024) {
        int i = base + tid;
        int v = (i < n_atoms) ? g_count[i] : 0;

        // inclusive scan within warp
        int x = v;
#pragma unroll
        for (int d = 1; d < 32; d <<= 1) {
            int t = __shfl_up_sync(0xFFFFFFFFu, x, d);
            if (lane >= d) x += t;
        }
        if (lane == 31) warp_off[wid] = x;
        __syncthreads();
        if (tid < 32) {
            int s = warp_off[tid];
            int y = s;
#pragma unroll
            for (int d = 1; d < 32; d <<= 1) {
                int t = __shfl_up_sync(0xFFFFFFFFu, y, d);
                if (tid >= d) y += t;
            }
            warp_off[tid] = y - s;   // exclusive warp offset
        }
        __syncthreads();

        int excl = (x - v) + warp_off[wid] + carry_s;
        if (i < n_atoms) g_offset[i] = excl;
        __syncthreads();             // all reads of carry_s done
        if (tid == 1023) carry_s += x + warp_off[31];   // chunk total
        __syncthreads();
    }
    if (tid == 0) g_nvalid = carry_s;
}

// ---------------------------------------------------------------------------
// Sort step 4: scatter edges into src-sorted record stream.
// g_offset is consumed destructively (atomicAdd cursor).
// ---------------------------------------------------------------------------
__global__ void scatter_kernel(const float* __restrict__ ev,
                               const int* __restrict__ eidx,
                               int n_edges, int n_atoms) {
    int e = blockIdx.x * blockDim.x + threadIdx.x;
    if (e >= n_edges) return;
    int src = eidx[e];
    int tgt = eidx[n_edges + e];
    if ((unsigned)src >= (unsigned)n_atoms || (unsigned)tgt >= (unsigned)n_atoms)
        return;
    int pos = atomicAdd(&g_offset[src], 1);
    float ex = __ldg(&ev[(size_t)e * 3 + 0]);
    float ey = __ldg(&ev[(size_t)e * 3 + 1]);
    float ez = __ldg(&ev[(size_t)e * 3 + 2]);
    g_rec4[pos]   = make_float4(ex, ey, ez, __int_as_float(src));
    g_rectgt[pos] = tgt;
}

// ---------------------------------------------------------------------------
// Kernel 5: sorted-edge contribution. 4 edges/warp, 8 lanes/edge.
// Consecutive records share src -> A-row gathers hit L1.
// ---------------------------------------------------------------------------
__global__ void __launch_bounds__(256)
edge_kernel(float* __restrict__ out) {
    const int n_valid = g_nvalid;
    const int lane  = threadIdx.x & 31;
    const int gwarp = (blockIdx.x * blockDim.x + threadIdx.x) >> 5;
    const int sub   = lane >> 3;
    const int el    = lane & 7;
    const int e     = gwarp * 4 + sub;
    if (e >= n_valid) return;                 // whole 8-lane group exits together

    const unsigned gmask = 0xFFu << (sub * 8);

    const float4 rec = __ldg(&g_rec4[e]);
    const int src = __float_as_int(rec.w);
    const int tgt = __ldg(&g_rectgt[e]);

    float r = sqrtf(rec.x * rec.x + rec.y * rec.y + rec.z * rec.z);
    float inv = 1.0f / fmaxf(r, 1e-12f);
    float x = rec.x * inv, y = rec.y * inv, z = rec.z * inv;
    float x2 = x * x, y2 = y * y, z2 = z * z;

    float Y[NIRR];
    Y[0]  = 0.28209479177387814f;
    Y[1]  = 0.4886025119029199f * y;
    Y[2]  = 0.4886025119029199f * z;
    Y[3]  = 0.4886025119029199f * x;
    Y[4]  = 1.0925484305920792f * x * y;
    Y[5]  = 1.0925484305920792f * y * z;
    Y[6]  = 0.31539156525252005f * (3.0f * z2 - 1.0f);
    Y[7]  = 1.0925484305920792f * x * z;
    Y[8]  = 0.5462742152960396f * (x2 - y2);
    Y[9]  = 0.5900435899266435f * y * (3.0f * x2 - y2);
    Y[10] = 2.890611442640554f  * x * y * z;
    Y[11] = 0.4570457994644658f * y * (5.0f * z2 - 1.0f);
    Y[12] = 0.3731763325901154f * z * (5.0f * z2 - 3.0f);
    Y[13] = 0.4570457994644658f * x * (5.0f * z2 - 1.0f);
    Y[14] = 1.445305721320277f  * z * (x2 - y2);
    Y[15] = 0.5900435899266435f * x * (x2 - 3.0f * y2);

    // Gather the A row: 8 uint4 per lane, batched for MLP.
    const uint4* __restrict__ Arow4 =
        (const uint4*)(g_Ah + (size_t)src * FANIN);
    uint4 v[8];
#pragma unroll
    for (int l = 0; l < 8; l++)
        v[l] = __ldg(&Arow4[l * 8 + el]);

    const int par = el >> 2;                  // irrep parity of this lane

    float acc[8];
#pragma unroll
    for (int i = 0; i < 8; i++) acc[i] = 0.f;

#pragma unroll
    for (int l = 0; l < 8; l++) {
        float yi = par ? Y[2 * l + 1] : Y[2 * l];
        float2 f0 = __half22float2(*(const __half2*)&v[l].x);
        float2 f1 = __half22float2(*(const __half2*)&v[l].y);
        float2 f2 = __half22float2(*(const __half2*)&v[l].z);
        float2 f3 = __half22float2(*(const __half2*)&v[l].w);
        acc[0] = fmaf(yi, f0.x, acc[0]); acc[1] = fmaf(yi, f0.y, acc[1]);
        acc[2] = fmaf(yi, f1.x, acc[2]); acc[3] = fmaf(yi, f1.y, acc[3]);
        acc[4] = fmaf(yi, f2.x, acc[4]); acc[5] = fmaf(yi, f2.y, acc[5]);
        acc[6] = fmaf(yi, f3.x, acc[6]); acc[7] = fmaf(yi, f3.y, acc[7]);
    }

    // Fold irrep parity: lanes el and el^4 hold the same 8 channels.
#pragma unroll
    for (int i = 0; i < 8; i++)
        acc[i] += __shfl_xor_sync(gmask, acc[i], 4);

    float r0 = par ? acc[4] : acc[0];
    float r1 = par ? acc[5] : acc[1];
    float r2 = par ? acc[6] : acc[2];
    float r3 = par ? acc[7] : acc[3];

    float* dst = &out[(size_t)tgt * OUTC + (el & 3) * 8 + par * 4];
    asm volatile("red.global.add.v4.f32 [%0], {%1, %2, %3, %4};"
                 :: "l"(dst), "f"(r0), "f"(r1), "f"(r2), "f"(r3)
                 : "memory");
}

// ---------------------------------------------------------------------------
// Launcher
// ---------------------------------------------------------------------------
extern "C" void kernel_launch(void* const* d_in, const int* in_sizes, int n_in,
                              void* d_out, int out_size) {
    const float* nf  = (const float*)d_in[0];
    const float* ev  = (const float*)d_in[1];
    const int*   ei  = (const int*)d_in[2];
    const float* W   = (const float*)d_in[3];
    const float* b   = (const float*)d_in[4];
    float*       out = (float*)d_out;

    const int n_atoms = in_sizes[0] / HID;
    const int n_edges = in_sizes[1] / 3;

    // out = b (broadcast), float4
    {
        int n4 = out_size / 4;
        init_out_kernel<<<(n4 + 255) / 256, 256>>>((float4*)out, (const float4*)b, n4);
    }

    // A = NF @ W' (fp16 output)
    {
        int grid = (n_atoms + 3) / 4;
        if (grid > 1184) grid = 1184;
        precompute_A_kernel<<<grid, 256>>>(nf, W, n_atoms);
    }

    // Counting sort of edges by src
    zero_count_kernel<<<(n_atoms + 255) / 256, 256>>>(n_atoms);
    hist_kernel<<<(n_edges + 255) / 256, 256>>>(ei, n_edges, n_atoms);
    scan_kernel<<<1, 1024>>>(n_atoms);
    scatter_kernel<<<(n_edges + 255) / 256, 256>>>(ev, ei, n_edges, n_atoms);

    // Sorted-edge gather + scatter: 4 edges/warp, 32 edges/block
    {
        int grid = (n_edges + 31) / 32;
        edge_kernel<<<grid, 256>>>(out);
    }
}

// round 6
// speedup vs baseline: 1.0079x; 1.0079x over previous
#include <cuda_runtime.h>
#include <cuda_fp16.h>
#include <cuda_bf16.h>

// Problem constants (fixed by the dataset)
#define HID    32
#define NIRR   16
#define OUTC   32
#define FANIN  (HID * NIRR)      // 512
#define MAX_ATOMS 50000
#define MAX_EDGES 800000

// Scratch: A[a][i*32+c] = sum_h nf[a][h] * W[(h*16+i)*32+c], stored fp16.
// Row = 512 halves = 1024 B = 8 x 128B lines. Line l holds irreps 2l, 2l+1.
__device__ __half g_Ah[(size_t)MAX_ATOMS * FANIN];

// Counting-sort scratch
__device__ int    g_count[MAX_ATOMS];
__device__ int    g_offset[MAX_ATOMS];       // destructive cursor
__device__ int    g_rowptr[MAX_ATOMS + 1];   // pristine CSR offsets
__device__ float4 g_rec4[MAX_EDGES];         // {ex, ey, ez, bitcast(tgt)}

// ---------------------------------------------------------------------------
// Kernel 0: out[t, c] = b[c]   (float4 vectorized)
// ---------------------------------------------------------------------------
__global__ void init_out_kernel(float4* __restrict__ out4,
                                const float4* __restrict__ b4, int n4) {
    int t = blockIdx.x * blockDim.x + threadIdx.x;
    if (t < n4) out4[t] = __ldg(&b4[t & 7]);
}

// ---------------------------------------------------------------------------
// Kernel 1: A = NF @ W'   (M=50000, K=32, N=512), output fp16.
// ---------------------------------------------------------------------------
__global__ void __launch_bounds__(256, 4)
precompute_A_kernel(const float* __restrict__ nf,
                    const float* __restrict__ W, int n_atoms) {
    const int tid = threadIdx.x;
    const int n0 = tid * 2;
    const int n1 = n0 + 1;

    float w0[HID], w1[HID];
#pragma unroll
    for (int h = 0; h < HID; h++) {
        w0[h] = __ldg(&W[(h * NIRR + (n0 >> 5)) * OUTC + (n0 & 31)]);
        w1[h] = __ldg(&W[(h * NIRR + (n1 >> 5)) * OUTC + (n1 & 31)]);
    }

    __shared__ float snf[4 * HID];

    for (int a0 = blockIdx.x * 4; a0 < n_atoms; a0 += gridDim.x * 4) {
        __syncthreads();
        if (tid < 4 * HID) {
            int a = a0 + (tid >> 5);
            snf[tid] = (a < n_atoms) ? nf[(size_t)a * HID + (tid & 31)] : 0.0f;
        }
        __syncthreads();

        float acc00 = 0.f, acc01 = 0.f, acc10 = 0.f, acc11 = 0.f;
        float acc20 = 0.f, acc21 = 0.f, acc30 = 0.f, acc31 = 0.f;
#pragma unroll
        for (int h = 0; h < HID; h++) {
            float f0 = snf[0 * HID + h];
            float f1 = snf[1 * HID + h];
            float f2 = snf[2 * HID + h];
            float f3 = snf[3 * HID + h];
            acc00 = fmaf(f0, w0[h], acc00); acc01 = fmaf(f0, w1[h], acc01);
            acc10 = fmaf(f1, w0[h], acc10); acc11 = fmaf(f1, w1[h], acc11);
            acc20 = fmaf(f2, w0[h], acc20); acc21 = fmaf(f2, w1[h], acc21);
            acc30 = fmaf(f3, w0[h], acc30); acc31 = fmaf(f3, w1[h], acc31);
        }
        if (a0 + 0 < n_atoms)
            *(__half2*)&g_Ah[(size_t)(a0 + 0) * FANIN + n0] = __floats2half2_rn(acc00, acc01);
        if (a0 + 1 < n_atoms)
            *(__half2*)&g_Ah[(size_t)(a0 + 1) * FANIN + n0] = __floats2half2_rn(acc10, acc11);
        if (a0 + 2 < n_atoms)
            *(__half2*)&g_Ah[(size_t)(a0 + 2) * FANIN + n0] = __floats2half2_rn(acc20, acc21);
        if (a0 + 3 < n_atoms)
            *(__half2*)&g_Ah[(size_t)(a0 + 3) * FANIN + n0] = __floats2half2_rn(acc30, acc31);
    }
}

// ---------------------------------------------------------------------------
// Sort step 1: zero counters
// ---------------------------------------------------------------------------
__global__ void zero_count_kernel(int n_atoms) {
    int i = blockIdx.x * blockDim.x + threadIdx.x;
    if (i < n_atoms) g_count[i] = 0;
}

// ---------------------------------------------------------------------------
// Sort step 2: histogram over edge sources
// ---------------------------------------------------------------------------
__global__ void hist_kernel(const int* __restrict__ eidx,
                            int n_edges, int n_atoms) {
    int e = blockIdx.x * blockDim.x + threadIdx.x;
    if (e >= n_edges) return;
    int src = eidx[e];
    int tgt = eidx[n_edges + e];
    if ((unsigned)src < (unsigned)n_atoms && (unsigned)tgt < (unsigned)n_atoms)
        atomicAdd(&g_count[src], 1);
}

// ---------------------------------------------------------------------------
// Sort step 3: exclusive scan of g_count -> g_rowptr (pristine) + g_offset
// (cursor). Single block, 1024 threads, chunked.
// ---------------------------------------------------------------------------
__global__ void __launch_bounds__(1024, 1)
scan_kernel(int n_atoms) {
    __shared__ int warp_off[32];
    __shared__ int carry_s;
    const int tid  = threadIdx.x;
    const int lane = tid & 31;
    const int wid  = tid >> 5;
    if (tid == 0) carry_s = 0;
    __syncthreads();

    for (int base = 0; base < n_atoms; base += 1024) {
        int i = base + tid;
        int v = (i < n_atoms) ? g_count[i] : 0;

        int x = v;
#pragma unroll
        for (int d = 1; d < 32; d <<= 1) {
            int t = __shfl_up_sync(0xFFFFFFFFu, x, d);
            if (lane >= d) x += t;
        }
        if (lane == 31) warp_off[wid] = x;
        __syncthreads();
        if (tid < 32) {
            int s = warp_off[tid];
            int y = s;
#pragma unroll
            for (int d = 1; d < 32; d <<= 1) {
                int t = __shfl_up_sync(0xFFFFFFFFu, y, d);
                if (tid >= d) y += t;
            }
            warp_off[tid] = y - s;   // exclusive warp offset
        }
        __syncthreads();

        int excl = (x - v) + warp_off[wid] + carry_s;
        if (i < n_atoms) {
            g_rowptr[i] = excl;
            g_offset[i] = excl;
        }
        __syncthreads();
        if (tid == 1023) carry_s += x + warp_off[31];
        __syncthreads();
    }
    if (tid == 0) g_rowptr[n_atoms] = carry_s;
}

// ---------------------------------------------------------------------------
// Sort step 4: scatter edges into src-sorted record stream {x,y,z,tgt}.
// ---------------------------------------------------------------------------
__global__ void scatter_kernel(const float* __restrict__ ev,
                               const int* __restrict__ eidx,
                               int n_edges, int n_atoms) {
    int e = blockIdx.x * blockDim.x + threadIdx.x;
    if (e >= n_edges) return;
    int src = eidx[e];
    int tgt = eidx[n_edges + e];
    if ((unsigned)src >= (unsigned)n_atoms || (unsigned)tgt >= (unsigned)n_atoms)
        return;
    int pos = atomicAdd(&g_offset[src], 1);
    float ex = __ldg(&ev[(size_t)e * 3 + 0]);
    float ey = __ldg(&ev[(size_t)e * 3 + 1]);
    float ez = __ldg(&ev[(size_t)e * 3 + 2]);
    g_rec4[pos] = make_float4(ex, ey, ez, __int_as_float(tgt));
}

// ---------------------------------------------------------------------------
// Kernel 5: CSR edge contraction. One warp per src atom.
// The warp loads the src's A row ONCE (8 x LDG.128, broadcast across the four
// 8-lane groups), then loops over the src's edges in chunks of 4:
//   sub = lane>>3 : edge slot in chunk;  el = lane&7 : lane within edge group
//   lane el's uint4 at line l covers irrep 2l+(el>>2), channels (el&3)*8..+7
// shfl_xor(4) folds irrep parity; each lane REDs 4 channels (one RED.v4/chunk).
// ---------------------------------------------------------------------------
__global__ void __launch_bounds__(256)
edge_kernel(float* __restrict__ out, int n_atoms) {
    const int warp_g = (blockIdx.x * blockDim.x + threadIdx.x) >> 5;
    if (warp_g >= n_atoms) return;
    const int src = warp_g;

    const int rs = __ldg(&g_rowptr[src]);
    const int re = __ldg(&g_rowptr[src + 1]);
    if (rs == re) return;

    const int lane = threadIdx.x & 31;
    const int sub  = lane >> 3;
    const int el   = lane & 7;
    const int par  = el >> 2;
    const unsigned gmask = 0xFFu << (sub * 8);

    // Load A row into registers (shared by all 4 subs -> broadcast LDG.128).
    const uint4* __restrict__ Arow4 = (const uint4*)(g_Ah + (size_t)src * FANIN);
    uint4 v[8];
#pragma unroll
    for (int l = 0; l < 8; l++)
        v[l] = __ldg(&Arow4[l * 8 + el]);

    for (int base = rs; base < re; base += 4) {
        const int e = base + sub;
        if (e < re) {
            const float4 rec = __ldg(&g_rec4[e]);
            const int tgt = __float_as_int(rec.w);

            float r = sqrtf(rec.x * rec.x + rec.y * rec.y + rec.z * rec.z);
            float inv = 1.0f / fmaxf(r, 1e-12f);
            float x = rec.x * inv, y = rec.y * inv, z = rec.z * inv;
            float x2 = x * x, y2 = y * y, z2 = z * z;

            float Y[NIRR];
            Y[0]  = 0.28209479177387814f;
            Y[1]  = 0.4886025119029199f * y;
            Y[2]  = 0.4886025119029199f * z;
            Y[3]  = 0.4886025119029199f * x;
            Y[4]  = 1.0925484305920792f * x * y;
            Y[5]  = 1.0925484305920792f * y * z;
            Y[6]  = 0.31539156525252005f * (3.0f * z2 - 1.0f);
            Y[7]  = 1.0925484305920792f * x * z;
            Y[8]  = 0.5462742152960396f * (x2 - y2);
            Y[9]  = 0.5900435899266435f * y * (3.0f * x2 - y2);
            Y[10] = 2.890611442640554f  * x * y * z;
            Y[11] = 0.4570457994644658f * y * (5.0f * z2 - 1.0f);
            Y[12] = 0.3731763325901154f * z * (5.0f * z2 - 3.0f);
            Y[13] = 0.4570457994644658f * x * (5.0f * z2 - 1.0f);
            Y[14] = 1.445305721320277f  * z * (x2 - y2);
            Y[15] = 0.5900435899266435f * x * (x2 - 3.0f * y2);

            float acc[8];
#pragma unroll
            for (int i = 0; i < 8; i++) acc[i] = 0.f;

#pragma unroll
            for (int l = 0; l < 8; l++) {
                float yi = par ? Y[2 * l + 1] : Y[2 * l];
                float2 f0 = __half22float2(*(const __half2*)&v[l].x);
                float2 f1 = __half22float2(*(const __half2*)&v[l].y);
                float2 f2 = __half22float2(*(const __half2*)&v[l].z);
                float2 f3 = __half22float2(*(const __half2*)&v[l].w);
                acc[0] = fmaf(yi, f0.x, acc[0]); acc[1] = fmaf(yi, f0.y, acc[1]);
                acc[2] = fmaf(yi, f1.x, acc[2]); acc[3] = fmaf(yi, f1.y, acc[3]);
                acc[4] = fmaf(yi, f2.x, acc[4]); acc[5] = fmaf(yi, f2.y, acc[5]);
                acc[6] = fmaf(yi, f3.x, acc[6]); acc[7] = fmaf(yi, f3.y, acc[7]);
            }

            // Fold irrep parity: lanes el and el^4 hold the same 8 channels.
#pragma unroll
            for (int i = 0; i < 8; i++)
                acc[i] += __shfl_xor_sync(gmask, acc[i], 4);

            float r0 = par ? acc[4] : acc[0];
            float r1 = par ? acc[5] : acc[1];
            float r2 = par ? acc[6] : acc[2];
            float r3 = par ? acc[7] : acc[3];

            float* dst = &out[(size_t)tgt * OUTC + (el & 3) * 8 + par * 4];
            asm volatile("red.global.add.v4.f32 [%0], {%1, %2, %3, %4};"
                         :: "l"(dst), "f"(r0), "f"(r1), "f"(r2), "f"(r3)
                         : "memory");
        }
    }
}

// ---------------------------------------------------------------------------
// Launcher
// ---------------------------------------------------------------------------
extern "C" void kernel_launch(void* const* d_in, const int* in_sizes, int n_in,
                              void* d_out, int out_size) {
    const float* nf  = (const float*)d_in[0];
    const float* ev  = (const float*)d_in[1];
    const int*   ei  = (const int*)d_in[2];
    const float* W   = (const float*)d_in[3];
    const float* b   = (const float*)d_in[4];
    float*       out = (float*)d_out;

    const int n_atoms = in_sizes[0] / HID;
    const int n_edges = in_sizes[1] / 3;

    // out = b (broadcast), float4
    {
        int n4 = out_size / 4;
        init_out_kernel<<<(n4 + 255) / 256, 256>>>((float4*)out, (const float4*)b, n4);
    }

    // A = NF @ W' (fp16 output)
    {
        int grid = (n_atoms + 3) / 4;
        if (grid > 1184) grid = 1184;
        precompute_A_kernel<<<grid, 256>>>(nf, W, n_atoms);
    }

    // Counting sort of edges by src -> CSR
    zero_count_kernel<<<(n_atoms + 255) / 256, 256>>>(n_atoms);
    hist_kernel<<<(n_edges + 255) / 256, 256>>>(ei, n_edges, n_atoms);
    scan_kernel<<<1, 1024>>>(n_atoms);
    scatter_kernel<<<(n_edges + 255) / 256, 256>>>(ev, ei, n_edges, n_atoms);

    // CSR contraction: one warp per src atom (8 warps/block)
    {
        int grid = (n_atoms + 7) / 8;
        edge_kernel<<<grid, 256>>>(out, n_atoms);
    }
}

// round 7
// speedup vs baseline: 1.1831x; 1.1739x over previous
#include <cuda_runtime.h>
#include <cuda_fp16.h>
#include <cuda_bf16.h>

// Problem constants (fixed by the dataset)
#define HID    32
#define NIRR   16
#define OUTC   32
#define FANIN  (HID * NIRR)      // 512
#define MAX_ATOMS 50000
#define MAX_EDGES 800000
#define SCAN_BLK 256
#define MAX_SCAN_BLOCKS 512      // ceil(50000/256)=196 < 512

// Scratch: A[a][i*32+c] = sum_h nf[a][h] * W[(h*16+i)*32+c], stored fp16.
// Row = 512 halves = 1024 B = 8 x 128B lines. Line l holds irreps 2l, 2l+1.
__device__ __half g_Ah[(size_t)MAX_ATOMS * FANIN];

// Counting-sort scratch
__device__ int    g_count[MAX_ATOMS];
__device__ int    g_offset[MAX_ATOMS];       // destructive cursor
__device__ int    g_rowptr[MAX_ATOMS + 1];   // pristine CSR offsets
__device__ int    g_bsum[MAX_SCAN_BLOCKS];   // per-block sums
__device__ int    g_boff[MAX_SCAN_BLOCKS];   // per-block exclusive offsets
__device__ float4 g_rec4[MAX_EDGES];         // {ex, ey, ez, bitcast(tgt)}

// ---------------------------------------------------------------------------
// Kernel 0: out[t, c] = b[c]   (float4 vectorized)
// ---------------------------------------------------------------------------
__global__ void init_out_kernel(float4* __restrict__ out4,
                                const float4* __restrict__ b4, int n4) {
    int t = blockIdx.x * blockDim.x + threadIdx.x;
    if (t < n4) out4[t] = __ldg(&b4[t & 7]);
}

// ---------------------------------------------------------------------------
// Kernel 1: A = NF @ W'   (M=50000, K=32, N=512), output fp16.
// ---------------------------------------------------------------------------
__global__ void __launch_bounds__(256, 4)
precompute_A_kernel(const float* __restrict__ nf,
                    const float* __restrict__ W, int n_atoms) {
    const int tid = threadIdx.x;
    const int n0 = tid * 2;
    const int n1 = n0 + 1;

    float w0[HID], w1[HID];
#pragma unroll
    for (int h = 0; h < HID; h++) {
        w0[h] = __ldg(&W[(h * NIRR + (n0 >> 5)) * OUTC + (n0 & 31)]);
        w1[h] = __ldg(&W[(h * NIRR + (n1 >> 5)) * OUTC + (n1 & 31)]);
    }

    __shared__ float snf[4 * HID];

    for (int a0 = blockIdx.x * 4; a0 < n_atoms; a0 += gridDim.x * 4) {
        __syncthreads();
        if (tid < 4 * HID) {
            int a = a0 + (tid >> 5);
            snf[tid] = (a < n_atoms) ? nf[(size_t)a * HID + (tid & 31)] : 0.0f;
        }
        __syncthreads();

        float acc00 = 0.f, acc01 = 0.f, acc10 = 0.f, acc11 = 0.f;
        float acc20 = 0.f, acc21 = 0.f, acc30 = 0.f, acc31 = 0.f;
#pragma unroll
        for (int h = 0; h < HID; h++) {
            float f0 = snf[0 * HID + h];
            float f1 = snf[1 * HID + h];
            float f2 = snf[2 * HID + h];
            float f3 = snf[3 * HID + h];
            acc00 = fmaf(f0, w0[h], acc00); acc01 = fmaf(f0, w1[h], acc01);
            acc10 = fmaf(f1, w0[h], acc10); acc11 = fmaf(f1, w1[h], acc11);
            acc20 = fmaf(f2, w0[h], acc20); acc21 = fmaf(f2, w1[h], acc21);
            acc30 = fmaf(f3, w0[h], acc30); acc31 = fmaf(f3, w1[h], acc31);
        }
        if (a0 + 0 < n_atoms)
            *(__half2*)&g_Ah[(size_t)(a0 + 0) * FANIN + n0] = __floats2half2_rn(acc00, acc01);
        if (a0 + 1 < n_atoms)
            *(__half2*)&g_Ah[(size_t)(a0 + 1) * FANIN + n0] = __floats2half2_rn(acc10, acc11);
        if (a0 + 2 < n_atoms)
            *(__half2*)&g_Ah[(size_t)(a0 + 2) * FANIN + n0] = __floats2half2_rn(acc20, acc21);
        if (a0 + 3 < n_atoms)
            *(__half2*)&g_Ah[(size_t)(a0 + 3) * FANIN + n0] = __floats2half2_rn(acc30, acc31);
    }
}

// ---------------------------------------------------------------------------
// Sort step 1: zero counters
// ---------------------------------------------------------------------------
__global__ void zero_count_kernel(int n_atoms) {
    int i = blockIdx.x * blockDim.x + threadIdx.x;
    if (i < n_atoms) g_count[i] = 0;
}

// ---------------------------------------------------------------------------
// Sort step 2: histogram over edge sources
// ---------------------------------------------------------------------------
__global__ void hist_kernel(const int* __restrict__ eidx,
                            int n_edges, int n_atoms) {
    int e = blockIdx.x * blockDim.x + threadIdx.x;
    if (e >= n_edges) return;
    int src = eidx[e];
    int tgt = eidx[n_edges + e];
    if ((unsigned)src < (unsigned)n_atoms && (unsigned)tgt < (unsigned)n_atoms)
        atomicAdd(&g_count[src], 1);
}

// ---------------------------------------------------------------------------
// Block-local exclusive scan helper (256 threads).
// Returns exclusive prefix of v within the block; *total = block sum.
// ---------------------------------------------------------------------------
__device__ __forceinline__ int block_excl_scan_256(int v, int* total) {
    __shared__ int wsum[8];
    const int tid  = threadIdx.x;
    const int lane = tid & 31;
    const int wid  = tid >> 5;
    int x = v;
#pragma unroll
    for (int d = 1; d < 32; d <<= 1) {
        int t = __shfl_up_sync(0xFFFFFFFFu, x, d);
        if (lane >= d) x += t;
    }
    if (lane == 31) wsum[wid] = x;
    __syncthreads();
    if (tid < 8) {
        int s = wsum[tid];
        int y = s;
#pragma unroll
        for (int d = 1; d < 8; d <<= 1) {
            int t = __shfl_up_sync(0xFFu, y, d);
            if (tid >= d) y += t;
        }
        wsum[tid] = y - s;           // exclusive warp offsets
        if (tid == 7) wsum[7] = y - s;  // (same value; keep simple)
    }
    __syncthreads();
    int excl = (x - v) + wsum[wid];
    // block total = excl of last thread + its value, computed via shfl from
    // last warp: easier to recompute via shared
    __shared__ int tot_s;
    if (tid == 255) tot_s = excl + v;
    __syncthreads();
    *total = tot_s;
    return excl;
}

// ---------------------------------------------------------------------------
// Sort step 3a: per-block local exclusive scan of g_count -> g_rowptr (local),
// block sums -> g_bsum.
// ---------------------------------------------------------------------------
__global__ void __launch_bounds__(SCAN_BLK)
scan1_kernel(int n_atoms) {
    int i = blockIdx.x * SCAN_BLK + threadIdx.x;
    int v = (i < n_atoms) ? g_count[i] : 0;
    int total;
    int excl = block_excl_scan_256(v, &total);
    if (i < n_atoms) g_rowptr[i] = excl;
    if (threadIdx.x == 0) g_bsum[blockIdx.x] = total;
}

// ---------------------------------------------------------------------------
// Sort step 3b: scan of block sums (single block of 256 >= nblocks).
// ---------------------------------------------------------------------------
__global__ void __launch_bounds__(SCAN_BLK)
scan2_kernel(int nblocks, int n_atoms) {
    int v = (threadIdx.x < nblocks) ? g_bsum[threadIdx.x] : 0;
    int total;
    int excl = block_excl_scan_256(v, &total);
    if (threadIdx.x < nblocks) g_boff[threadIdx.x] = excl;
    if (threadIdx.x == 0) g_rowptr[n_atoms] = total;
}

// ---------------------------------------------------------------------------
// Sort step 3c: add block offsets; produce pristine rowptr + cursor copy.
// ---------------------------------------------------------------------------
__global__ void __launch_bounds__(SCAN_BLK)
scan3_kernel(int n_atoms) {
    int i = blockIdx.x * SCAN_BLK + threadIdx.x;
    if (i < n_atoms) {
        int r = g_rowptr[i] + g_boff[blockIdx.x];
        g_rowptr[i] = r;
        g_offset[i] = r;
    }
}

// ---------------------------------------------------------------------------
// Sort step 4: scatter edges into src-sorted record stream {x,y,z,tgt}.
// ---------------------------------------------------------------------------
__global__ void scatter_kernel(const float* __restrict__ ev,
                               const int* __restrict__ eidx,
                               int n_edges, int n_atoms) {
    int e = blockIdx.x * blockDim.x + threadIdx.x;
    if (e >= n_edges) return;
    int src = eidx[e];
    int tgt = eidx[n_edges + e];
    if ((unsigned)src >= (unsigned)n_atoms || (unsigned)tgt >= (unsigned)n_atoms)
        return;
    int pos = atomicAdd(&g_offset[src], 1);
    float ex = __ldg(&ev[(size_t)e * 3 + 0]);
    float ey = __ldg(&ev[(size_t)e * 3 + 1]);
    float ez = __ldg(&ev[(size_t)e * 3 + 2]);
    g_rec4[pos] = make_float4(ex, ey, ez, __int_as_float(tgt));
}

// ---------------------------------------------------------------------------
// Kernel 5: CSR edge contraction. One warp per src atom.
// Warp loads the src's A row ONCE into registers (8 x LDG.128; the four
// 8-lane groups read the same lines -> L1 broadcast), then loops over the
// src's edges in chunks of 4 (sub = lane>>3 edge slot, el = lane&7):
// lane el's uint4 at line l covers irrep 2l+(el>>2), channels (el&3)*8..+7.
// shfl_xor(4) folds irrep parity; each lane REDs 4 channels (1 RED.v4/chunk).
// ---------------------------------------------------------------------------
__global__ void __launch_bounds__(256)
edge_kernel(float* __restrict__ out, int n_atoms) {
    const int warp_g = (blockIdx.x * blockDim.x + threadIdx.x) >> 5;
    if (warp_g >= n_atoms) return;
    const int src = warp_g;

    const int rs = __ldg(&g_rowptr[src]);
    const int re = __ldg(&g_rowptr[src + 1]);
    if (rs == re) return;

    const int lane = threadIdx.x & 31;
    const int sub  = lane >> 3;
    const int el   = lane & 7;
    const int par  = el >> 2;
    const unsigned gmask = 0xFFu << (sub * 8);

    const uint4* __restrict__ Arow4 = (const uint4*)(g_Ah + (size_t)src * FANIN);
    uint4 v[8];
#pragma unroll
    for (int l = 0; l < 8; l++)
        v[l] = __ldg(&Arow4[l * 8 + el]);

    for (int base = rs; base < re; base += 4) {
        const int e = base + sub;
        if (e < re) {
            const float4 rec = __ldg(&g_rec4[e]);
            const int tgt = __float_as_int(rec.w);

            float r = sqrtf(rec.x * rec.x + rec.y * rec.y + rec.z * rec.z);
            float inv = 1.0f / fmaxf(r, 1e-12f);
            float x = rec.x * inv, y = rec.y * inv, z = rec.z * inv;
            float x2 = x * x, y2 = y * y, z2 = z * z;

            float Y[NIRR];
            Y[0]  = 0.28209479177387814f;
            Y[1]  = 0.4886025119029199f * y;
            Y[2]  = 0.4886025119029199f * z;
            Y[3]  = 0.4886025119029199f * x;
            Y[4]  = 1.0925484305920792f * x * y;
            Y[5]  = 1.0925484305920792f * y * z;
            Y[6]  = 0.31539156525252005f * (3.0f * z2 - 1.0f);
            Y[7]  = 1.0925484305920792f * x * z;
            Y[8]  = 0.5462742152960396f * (x2 - y2);
            Y[9]  = 0.5900435899266435f * y * (3.0f * x2 - y2);
            Y[10] = 2.890611442640554f  * x * y * z;
            Y[11] = 0.4570457994644658f * y * (5.0f * z2 - 1.0f);
            Y[12] = 0.3731763325901154f * z * (5.0f * z2 - 3.0f);
            Y[13] = 0.4570457994644658f * x * (5.0f * z2 - 1.0f);
            Y[14] = 1.445305721320277f  * z * (x2 - y2);
            Y[15] = 0.5900435899266435f * x * (x2 - 3.0f * y2);

            float acc[8];
#pragma unroll
            for (int i = 0; i < 8; i++) acc[i] = 0.f;

#pragma unroll
            for (int l = 0; l < 8; l++) {
                float yi = par ? Y[2 * l + 1] : Y[2 * l];
                float2 f0 = __half22float2(*(const __half2*)&v[l].x);
                float2 f1 = __half22float2(*(const __half2*)&v[l].y);
                float2 f2 = __half22float2(*(const __half2*)&v[l].z);
                float2 f3 = __half22float2(*(const __half2*)&v[l].w);
                acc[0] = fmaf(yi, f0.x, acc[0]); acc[1] = fmaf(yi, f0.y, acc[1]);
                acc[2] = fmaf(yi, f1.x, acc[2]); acc[3] = fmaf(yi, f1.y, acc[3]);
                acc[4] = fmaf(yi, f2.x, acc[4]); acc[5] = fmaf(yi, f2.y, acc[5]);
                acc[6] = fmaf(yi, f3.x, acc[6]); acc[7] = fmaf(yi, f3.y, acc[7]);
            }

#pragma unroll
            for (int i = 0; i < 8; i++)
                acc[i] += __shfl_xor_sync(gmask, acc[i], 4);

            float r0 = par ? acc[4] : acc[0];
            float r1 = par ? acc[5] : acc[1];
            float r2 = par ? acc[6] : acc[2];
            float r3 = par ? acc[7] : acc[3];

            float* dst = &out[(size_t)tgt * OUTC + (el & 3) * 8 + par * 4];
            asm volatile("red.global.add.v4.f32 [%0], {%1, %2, %3, %4};"
                         :: "l"(dst), "f"(r0), "f"(r1), "f"(r2), "f"(r3)
                         : "memory");
        }
    }
}

// ---------------------------------------------------------------------------
// Launcher
// ---------------------------------------------------------------------------
extern "C" void kernel_launch(void* const* d_in, const int* in_sizes, int n_in,
                              void* d_out, int out_size) {
    const float* nf  = (const float*)d_in[0];
    const float* ev  = (const float*)d_in[1];
    const int*   ei  = (const int*)d_in[2];
    const float* W   = (const float*)d_in[3];
    const float* b   = (const float*)d_in[4];
    float*       out = (float*)d_out;

    const int n_atoms = in_sizes[0] / HID;
    const int n_edges = in_sizes[1] / 3;

    // out = b (broadcast), float4
    {
        int n4 = out_size / 4;
        init_out_kernel<<<(n4 + 255) / 256, 256>>>((float4*)out, (const float4*)b, n4);
    }

    // A = NF @ W' (fp16 output)
    {
        int grid = (n_atoms + 3) / 4;
        if (grid > 1184) grid = 1184;
        precompute_A_kernel<<<grid, 256>>>(nf, W, n_atoms);
    }

    // Counting sort of edges by src -> CSR (parallel 3-phase scan)
    const int nblocks = (n_atoms + SCAN_BLK - 1) / SCAN_BLK;
    zero_count_kernel<<<(n_atoms + 255) / 256, 256>>>(n_atoms);
    hist_kernel<<<(n_edges + 255) / 256, 256>>>(ei, n_edges, n_atoms);
    scan1_kernel<<<nblocks, SCAN_BLK>>>(n_atoms);
    scan2_kernel<<<1, SCAN_BLK>>>(nblocks, n_atoms);
    scan3_kernel<<<nblocks, SCAN_BLK>>>(n_atoms);
    scatter_kernel<<<(n_edges + 255) / 256, 256>>>(ev, ei, n_edges, n_atoms);

    // CSR contraction: one warp per src atom (8 warps/block)
    {
        int grid = (n_atoms + 7) / 8;
        edge_kernel<<<grid, 256>>>(out, n_atoms);
    }
}

// round 8
// speedup vs baseline: 1.8816x; 1.5904x over previous
#include <cuda_runtime.h>
#include <cuda_fp16.h>
#include <cuda_bf16.h>

// Problem constants (fixed by the dataset)
#define HID    32
#define NIRR   16
#define OUTC   32
#define FANIN  (HID * NIRR)      // 512
#define MAX_ATOMS 50000

// Scratch: A[a][i*32+c] = sum_h nf[a][h] * W[(h*16+i)*32+c], stored fp16.
// Row = 512 halves = 1024 B = 8 x 128B lines. Line l holds irreps 2l, 2l+1.
__device__ __half g_Ah[(size_t)MAX_ATOMS * FANIN];

// ---------------------------------------------------------------------------
// Kernel 0: out[t, c] = b[c]   (float4 vectorized)
// ---------------------------------------------------------------------------
__global__ void init_out_kernel(float4* __restrict__ out4,
                                const float4* __restrict__ b4, int n4) {
    int t = blockIdx.x * blockDim.x + threadIdx.x;
    if (t < n4) out4[t] = __ldg(&b4[t & 7]);
}

// ---------------------------------------------------------------------------
// Kernel 1: A = NF @ W'  via mma.sync m16n8k16 (fp16 in, fp32 accum).
// Block = 128 threads (4 warps), M-tile = 64 rows, N = 512 in 8 chunks of 64.
//   sW [k=32][n=512] fp16, padded stride 520 halves (conflict-free ldmatrix)
//   sNF[m=64][k=32]  fp16, padded stride 40 halves
// Warp w owns rows w*16..w*16+15. A-frags loaded once (2 k-steps), held in
// regs. Per chunk, per n8-tile: one ldmatrix.x4.trans (B frags for both
// k-steps) + 2 HMMA. C written to g_Ah as half2 per lane.
// ---------------------------------------------------------------------------
#define PRE_BM 64
#define SW_STRIDE 520
#define SNF_STRIDE 40

__global__ void __launch_bounds__(128)
precompute_mma_kernel(const float* __restrict__ nf,
                      const float* __restrict__ W, int n_atoms) {
    __shared__ __half sW[HID * SW_STRIDE];      // 33,280 B
    __shared__ __half sNF[PRE_BM * SNF_STRIDE]; // 5,120 B

    const int tid  = threadIdx.x;
    const int warp = tid >> 5;
    const int lane = tid & 31;
    const int m_base = blockIdx.x * PRE_BM;

    // Stage W: src f32 flat f = (h*16+i)*32+c = h*512 + (i*32+c).
    // sW[h*520 + (i*32+c)] — row h holds the n-index (i*32+c) directly.
    for (int f = tid; f < FANIN * OUTC / 1; f += 128) {      // 16384 elems? no:
        ;
    }
    // (corrected loop below — W has FANIN*OUTC = 512*32 = 16384 elements)
    for (int f = tid; f < 16384; f += 128) {
        int h   = f >> 9;          // 0..31
        int rem = f & 511;         // i*32+c
        sW[h * SW_STRIDE + rem] = __float2half(__ldg(&W[f]));
    }
    // Stage nf tile (zero-padded beyond n_atoms)
    for (int f = tid; f < PRE_BM * HID; f += 128) {
        int r = f >> 5, h = f & 31;
        int a = m_base + r;
        sNF[r * SNF_STRIDE + h] =
            (a < n_atoms) ? __float2half(nf[(size_t)a * HID + h]) : __half(0.0f);
    }
    __syncthreads();

    // A fragments: m16k16 x 2 k-steps, canonical row-major ldmatrix.x4
    unsigned afrag[2][4];
    {
        int row  = warp * 16 + (lane & 15);
        int colh = (lane >> 4) * 8;
#pragma unroll
        for (int ks = 0; ks < 2; ks++) {
            unsigned addr = (unsigned)__cvta_generic_to_shared(
                &sNF[row * SNF_STRIDE + ks * 16 + colh]);
            asm volatile(
                "ldmatrix.sync.aligned.m8n8.x4.shared.b16 {%0,%1,%2,%3}, [%4];"
                : "=r"(afrag[ks][0]), "=r"(afrag[ks][1]),
                  "=r"(afrag[ks][2]), "=r"(afrag[ks][3])
                : "r"(addr));
        }
    }

    const int r0 = lane >> 2;          // C frag row within m16
    const int cb = (lane & 3) * 2;     // C frag col pair within n8
    const int ga0 = m_base + warp * 16 + r0;
    const int ga1 = ga0 + 8;

#pragma unroll
    for (int nc = 0; nc < 8; nc++) {
        float c[8][4];
#pragma unroll
        for (int t = 0; t < 8; t++) {
            c[t][0] = 0.f; c[t][1] = 0.f; c[t][2] = 0.f; c[t][3] = 0.f;
        }
#pragma unroll
        for (int t = 0; t < 8; t++) {
            // B frags for n8-tile t, both k-steps: rows k = lane (0..31)
            unsigned b[4];
            unsigned addr = (unsigned)__cvta_generic_to_shared(
                &sW[lane * SW_STRIDE + nc * 64 + t * 8]);
            asm volatile(
                "ldmatrix.sync.aligned.m8n8.x4.trans.shared.b16 {%0,%1,%2,%3}, [%4];"
                : "=r"(b[0]), "=r"(b[1]), "=r"(b[2]), "=r"(b[3])
                : "r"(addr));
            asm volatile(
                "mma.sync.aligned.m16n8k16.row.col.f32.f16.f16.f32 "
                "{%0,%1,%2,%3}, {%4,%5,%6,%7}, {%8,%9}, {%0,%1,%2,%3};"
                : "+f"(c[t][0]), "+f"(c[t][1]), "+f"(c[t][2]), "+f"(c[t][3])
                : "r"(afrag[0][0]), "r"(afrag[0][1]),
                  "r"(afrag[0][2]), "r"(afrag[0][3]),
                  "r"(b[0]), "r"(b[1]));
            asm volatile(
                "mma.sync.aligned.m16n8k16.row.col.f32.f16.f16.f32 "
                "{%0,%1,%2,%3}, {%4,%5,%6,%7}, {%8,%9}, {%0,%1,%2,%3};"
                : "+f"(c[t][0]), "+f"(c[t][1]), "+f"(c[t][2]), "+f"(c[t][3])
                : "r"(afrag[1][0]), "r"(afrag[1][1]),
                  "r"(afrag[1][2]), "r"(afrag[1][3]),
                  "r"(b[2]), "r"(b[3]));
        }
        // Store C as fp16 pairs
#pragma unroll
        for (int t = 0; t < 8; t++) {
            int colh = nc * 64 + t * 8 + cb;
            if (ga0 < n_atoms)
                *(__half2*)&g_Ah[(size_t)ga0 * FANIN + colh] =
                    __floats2half2_rn(c[t][0], c[t][1]);
            if (ga1 < n_atoms)
                *(__half2*)&g_Ah[(size_t)ga1 * FANIN + colh] =
                    __floats2half2_rn(c[t][2], c[t][3]);
        }
    }
}

// ---------------------------------------------------------------------------
// Kernel 2: per-edge contribution. 4 edges per warp, 8 lanes per edge.
//   sub = lane>>3 : edge slot;  el = lane&7 : lane within edge group
// 8 x LDG.128 per lane; lane el's uint4 at line l covers irrep 2l+(el>>2),
// channels (el&3)*8..+7. shfl_xor(4) folds irrep parity; each lane REDs
// 4 channels with one red.global.add.v4.f32.
// ---------------------------------------------------------------------------
__global__ void __launch_bounds__(256)
edge_kernel(const float* __restrict__ ev,
            const int* __restrict__ eidx,
            float* __restrict__ out,
            int n_edges, int n_atoms) {
    const int lane  = threadIdx.x & 31;
    const int gwarp = (blockIdx.x * blockDim.x + threadIdx.x) >> 5;
    const int sub   = lane >> 3;
    const int el    = lane & 7;
    const int e     = gwarp * 4 + sub;
    if (e >= n_edges) return;                    // 8-lane group exits together

    const unsigned gmask = 0xFFu << (sub * 8);

    const int src = eidx[e];
    const int tgt = eidx[n_edges + e];
    if ((unsigned)src >= (unsigned)n_atoms || (unsigned)tgt >= (unsigned)n_atoms)
        return;

    const float ex = __ldg(&ev[(size_t)e * 3 + 0]);
    const float ey = __ldg(&ev[(size_t)e * 3 + 1]);
    const float ez = __ldg(&ev[(size_t)e * 3 + 2]);

    float r = sqrtf(ex * ex + ey * ey + ez * ez);
    float inv = 1.0f / fmaxf(r, 1e-12f);
    float x = ex * inv, y = ey * inv, z = ez * inv;
    float x2 = x * x, y2 = y * y, z2 = z * z;

    float Y[NIRR];
    Y[0]  = 0.28209479177387814f;
    Y[1]  = 0.4886025119029199f * y;
    Y[2]  = 0.4886025119029199f * z;
    Y[3]  = 0.4886025119029199f * x;
    Y[4]  = 1.0925484305920792f * x * y;
    Y[5]  = 1.0925484305920792f * y * z;
    Y[6]  = 0.31539156525252005f * (3.0f * z2 - 1.0f);
    Y[7]  = 1.0925484305920792f * x * z;
    Y[8]  = 0.5462742152960396f * (x2 - y2);
    Y[9]  = 0.5900435899266435f * y * (3.0f * x2 - y2);
    Y[10] = 2.890611442640554f  * x * y * z;
    Y[11] = 0.4570457994644658f * y * (5.0f * z2 - 1.0f);
    Y[12] = 0.3731763325901154f * z * (5.0f * z2 - 3.0f);
    Y[13] = 0.4570457994644658f * x * (5.0f * z2 - 1.0f);
    Y[14] = 1.445305721320277f  * z * (x2 - y2);
    Y[15] = 0.5900435899266435f * x * (x2 - 3.0f * y2);

    const uint4* __restrict__ Arow4 =
        (const uint4*)(g_Ah + (size_t)src * FANIN);
    uint4 v[8];
#pragma unroll
    for (int l = 0; l < 8; l++)
        v[l] = __ldg(&Arow4[l * 8 + el]);

    const int par = el >> 2;

    float acc[8];
#pragma unroll
    for (int i = 0; i < 8; i++) acc[i] = 0.f;

#pragma unroll
    for (int l = 0; l < 8; l++) {
        float yi = par ? Y[2 * l + 1] : Y[2 * l];
        float2 f0 = __half22float2(*(const __half2*)&v[l].x);
        float2 f1 = __half22float2(*(const __half2*)&v[l].y);
        float2 f2 = __half22float2(*(const __half2*)&v[l].z);
        float2 f3 = __half22float2(*(const __half2*)&v[l].w);
        acc[0] = fmaf(yi, f0.x, acc[0]); acc[1] = fmaf(yi, f0.y, acc[1]);
        acc[2] = fmaf(yi, f1.x, acc[2]); acc[3] = fmaf(yi, f1.y, acc[3]);
        acc[4] = fmaf(yi, f2.x, acc[4]); acc[5] = fmaf(yi, f2.y, acc[5]);
        acc[6] = fmaf(yi, f3.x, acc[6]); acc[7] = fmaf(yi, f3.y, acc[7]);
    }

#pragma unroll
    for (int i = 0; i < 8; i++)
        acc[i] += __shfl_xor_sync(gmask, acc[i], 4);

    float r0 = par ? acc[4] : acc[0];
    float r1 = par ? acc[5] : acc[1];
    float r2 = par ? acc[6] : acc[2];
    float r3 = par ? acc[7] : acc[3];

    float* dst = &out[(size_t)tgt * OUTC + (el & 3) * 8 + par * 4];
    asm volatile("red.global.add.v4.f32 [%0], {%1, %2, %3, %4};"
                 :: "l"(dst), "f"(r0), "f"(r1), "f"(r2), "f"(r3)
                 : "memory");
}

// ---------------------------------------------------------------------------
// Launcher
// Inputs (metadata order): node_features f32 [n_atoms,32], edge_vectors f32
// [n_edges,3], edge_index int32 [2,n_edges], W f32 [512,32], b f32 [32].
// Output: f32 [n_atoms, 32].
// ---------------------------------------------------------------------------
extern "C" void kernel_launch(void* const* d_in, const int* in_sizes, int n_in,
                              void* d_out, int out_size) {
    const float* nf  = (const float*)d_in[0];
    const float* ev  = (const float*)d_in[1];
    const int*   ei  = (const int*)d_in[2];
    const float* W   = (const float*)d_in[3];
    const float* b   = (const float*)d_in[4];
    float*       out = (float*)d_out;

    const int n_atoms = in_sizes[0] / HID;
    const int n_edges = in_sizes[1] / 3;

    // out = b (broadcast), float4
    {
        int n4 = out_size / 4;
        init_out_kernel<<<(n4 + 255) / 256, 256>>>((float4*)out, (const float4*)b, n4);
    }

    // A = NF @ W' via tensor cores (fp16 in, fp32 accum, fp16 out)
    {
        int grid = (n_atoms + PRE_BM - 1) / PRE_BM;
        precompute_mma_kernel<<<grid, 128>>>(nf, W, n_atoms);
    }

    // per-edge gather + scatter: 4 edges/warp, 32 edges/block
    {
        int grid = (n_edges + 31) / 32;
        edge_kernel<<<grid, 256>>>(ev, ei, out, n_edges, n_atoms);
    }
}

// round 9
// speedup vs baseline: 2.3887x; 1.2695x over previous
#include <cuda_runtime.h>
#include <cuda_fp16.h>
#include <cuda_bf16.h>

// Problem constants (fixed by the dataset)
#define HID    32
#define NIRR   16
#define OUTC   32
#define FANIN  (HID * NIRR)      // 512
#define MAX_ATOMS 50000

// Scratch: A[a][i*32+c] = sum_h nf[a][h] * W[(h*16+i)*32+c], stored fp16.
// Row = 512 halves = 1024 B = 8 x 128B lines. Line l holds irreps 2l, 2l+1.
__device__ __half g_Ah[(size_t)MAX_ATOMS * FANIN];

// ---------------------------------------------------------------------------
// Kernel 0: out[t, c] = b[c]   (float4 vectorized)
// ---------------------------------------------------------------------------
__global__ void init_out_kernel(float4* __restrict__ out4,
                                const float4* __restrict__ b4, int n4) {
    int t = blockIdx.x * blockDim.x + threadIdx.x;
    if (t < n4) out4[t] = __ldg(&b4[t & 7]);
}

// ---------------------------------------------------------------------------
// Kernel 1: A = NF @ W'  via mma.sync m16n8k16 (fp16 in, fp32 accum).
// Block = 128 threads (4 warps), M-tile = 64 rows, N = 512 in 8 chunks of 64.
//   sW [k=32][n=512] fp16, stride 520 halves (conflict-free ldmatrix.trans)
//   sNF[m=64][k=32]  fp16, stride 40 halves
//   sStage[warp][16 x 72] fp16 epilogue staging (stride 72 -> +4 banks/row)
// Warp w owns rows w*16..w*16+15. A-frags held in regs across all N.
// Epilogue: STS.32 frags -> smem, then coalesced STG.128 to g_Ah.
// ---------------------------------------------------------------------------
#define PRE_BM 64
#define SW_STRIDE 520
#define SNF_STRIDE 40
#define STG_STRIDE 72

__global__ void __launch_bounds__(128)
precompute_mma_kernel(const float* __restrict__ nf,
                      const float* __restrict__ W, int n_atoms) {
    __shared__ __half sW[HID * SW_STRIDE];        // 33,280 B
    __shared__ __half sNF[PRE_BM * SNF_STRIDE];   //  5,120 B
    __shared__ __half sStage[4][16 * STG_STRIDE]; //  9,216 B

    const int tid  = threadIdx.x;
    const int warp = tid >> 5;
    const int lane = tid & 31;
    const int m_base = blockIdx.x * PRE_BM;

    // Stage W via float4: 16384 f32 = 4096 float4. flat = (h*16+i)*32+c.
    {
        const float4* __restrict__ W4 = (const float4*)W;
        for (int i = tid; i < 4096; i += 128) {
            float4 w = __ldg(&W4[i]);
            int base = i * 4;
            int h = base >> 9, rem = base & 511;
            *(__half2*)&sW[h * SW_STRIDE + rem]     = __floats2half2_rn(w.x, w.y);
            *(__half2*)&sW[h * SW_STRIDE + rem + 2] = __floats2half2_rn(w.z, w.w);
        }
    }
    // Stage nf tile via float4 (zero-padded beyond n_atoms)
    {
        const float4* __restrict__ nf4 = (const float4*)nf;
        for (int i = tid; i < PRE_BM * HID / 4; i += 128) {   // 512 float4
            int r = i >> 3, q = i & 7;
            int a = m_base + r;
            float4 v = (a < n_atoms) ? __ldg(&nf4[(size_t)a * 8 + q])
                                     : make_float4(0.f, 0.f, 0.f, 0.f);
            *(__half2*)&sNF[r * SNF_STRIDE + q * 4]     = __floats2half2_rn(v.x, v.y);
            *(__half2*)&sNF[r * SNF_STRIDE + q * 4 + 2] = __floats2half2_rn(v.z, v.w);
        }
    }
    __syncthreads();

    // A fragments: m16k16 x 2 k-steps, canonical row-major ldmatrix.x4
    unsigned afrag[2][4];
    {
        int row  = warp * 16 + (lane & 15);
        int colh = (lane >> 4) * 8;
#pragma unroll
        for (int ks = 0; ks < 2; ks++) {
            unsigned addr = (unsigned)__cvta_generic_to_shared(
                &sNF[row * SNF_STRIDE + ks * 16 + colh]);
            asm volatile(
                "ldmatrix.sync.aligned.m8n8.x4.shared.b16 {%0,%1,%2,%3}, [%4];"
                : "=r"(afrag[ks][0]), "=r"(afrag[ks][1]),
                  "=r"(afrag[ks][2]), "=r"(afrag[ks][3])
                : "r"(addr));
        }
    }

    const int r0 = lane >> 2;          // C frag row within m16
    const int cb = (lane & 3) * 2;     // C frag col pair within n8
    __half* __restrict__ st = sStage[warp];

#pragma unroll
    for (int nc = 0; nc < 8; nc++) {
        float c[8][4];
#pragma unroll
        for (int t = 0; t < 8; t++) {
            c[t][0] = 0.f; c[t][1] = 0.f; c[t][2] = 0.f; c[t][3] = 0.f;
        }
#pragma unroll
        for (int t = 0; t < 8; t++) {
            unsigned b[4];
            unsigned addr = (unsigned)__cvta_generic_to_shared(
                &sW[lane * SW_STRIDE + nc * 64 + t * 8]);
            asm volatile(
                "ldmatrix.sync.aligned.m8n8.x4.trans.shared.b16 {%0,%1,%2,%3}, [%4];"
                : "=r"(b[0]), "=r"(b[1]), "=r"(b[2]), "=r"(b[3])
                : "r"(addr));
            asm volatile(
                "mma.sync.aligned.m16n8k16.row.col.f32.f16.f16.f32 "
                "{%0,%1,%2,%3}, {%4,%5,%6,%7}, {%8,%9}, {%0,%1,%2,%3};"
                : "+f"(c[t][0]), "+f"(c[t][1]), "+f"(c[t][2]), "+f"(c[t][3])
                : "r"(afrag[0][0]), "r"(afrag[0][1]),
                  "r"(afrag[0][2]), "r"(afrag[0][3]),
                  "r"(b[0]), "r"(b[1]));
            asm volatile(
                "mma.sync.aligned.m16n8k16.row.col.f32.f16.f16.f32 "
                "{%0,%1,%2,%3}, {%4,%5,%6,%7}, {%8,%9}, {%0,%1,%2,%3};"
                : "+f"(c[t][0]), "+f"(c[t][1]), "+f"(c[t][2]), "+f"(c[t][3])
                : "r"(afrag[1][0]), "r"(afrag[1][1]),
                  "r"(afrag[1][2]), "r"(afrag[1][3]),
                  "r"(b[2]), "r"(b[3]));
        }
        // Stage C tile (16 x 64 halves) into padded smem
#pragma unroll
        for (int t = 0; t < 8; t++) {
            *(__half2*)&st[r0 * STG_STRIDE + t * 8 + cb] =
                __floats2half2_rn(c[t][0], c[t][1]);
            *(__half2*)&st[(r0 + 8) * STG_STRIDE + t * 8 + cb] =
                __floats2half2_rn(c[t][2], c[t][3]);
        }
        __syncwarp();
        // Coalesced copy-out: 128 uint4 (16 rows x 8 uint4) per warp tile
#pragma unroll
        for (int j = 0; j < 4; j++) {
            int idx = j * 32 + lane;
            int row = idx >> 3, col = idx & 7;
            uint4 val = *(uint4*)&st[row * STG_STRIDE + col * 8];
            int ga = m_base + warp * 16 + row;
            if (ga < n_atoms)
                *(uint4*)&g_Ah[(size_t)ga * FANIN + nc * 64 + col * 8] = val;
        }
        __syncwarp();
    }
}

// ---------------------------------------------------------------------------
// Kernel 2: per-edge contribution. 4 edges per warp, 8 lanes per edge.
//   sub = lane>>3 : edge slot;  el = lane&7 : lane within edge group
// 8 x LDG.128 per lane; lane el's uint4 at line l covers irrep 2l+(el>>2),
// channels (el&3)*8..+7. shfl_xor(4) folds irrep parity; each lane REDs
// 4 channels with one red.global.add.v4.f32.
// ---------------------------------------------------------------------------
__global__ void __launch_bounds__(256)
edge_kernel(const float* __restrict__ ev,
            const int* __restrict__ eidx,
            float* __restrict__ out,
            int n_edges, int n_atoms) {
    const int lane  = threadIdx.x & 31;
    const int gwarp = (blockIdx.x * blockDim.x + threadIdx.x) >> 5;
    const int sub   = lane >> 3;
    const int el    = lane & 7;
    const int e     = gwarp * 4 + sub;
    if (e >= n_edges) return;                    // 8-lane group exits together

    const unsigned gmask = 0xFFu << (sub * 8);

    const int src = eidx[e];
    const int tgt = eidx[n_edges + e];
    if ((unsigned)src >= (unsigned)n_atoms || (unsigned)tgt >= (unsigned)n_atoms)
        return;

    const float ex = __ldg(&ev[(size_t)e * 3 + 0]);
    const float ey = __ldg(&ev[(size_t)e * 3 + 1]);
    const float ez = __ldg(&ev[(size_t)e * 3 + 2]);

    float r = sqrtf(ex * ex + ey * ey + ez * ez);
    float inv = 1.0f / fmaxf(r, 1e-12f);
    float x = ex * inv, y = ey * inv, z = ez * inv;
    float x2 = x * x, y2 = y * y, z2 = z * z;

    float Y[NIRR];
    Y[0]  = 0.28209479177387814f;
    Y[1]  = 0.4886025119029199f * y;
    Y[2]  = 0.4886025119029199f * z;
    Y[3]  = 0.4886025119029199f * x;
    Y[4]  = 1.0925484305920792f * x * y;
    Y[5]  = 1.0925484305920792f * y * z;
    Y[6]  = 0.31539156525252005f * (3.0f * z2 - 1.0f);
    Y[7]  = 1.0925484305920792f * x * z;
    Y[8]  = 0.5462742152960396f * (x2 - y2);
    Y[9]  = 0.5900435899266435f * y * (3.0f * x2 - y2);
    Y[10] = 2.890611442640554f  * x * y * z;
    Y[11] = 0.4570457994644658f * y * (5.0f * z2 - 1.0f);
    Y[12] = 0.3731763325901154f * z * (5.0f * z2 - 3.0f);
    Y[13] = 0.4570457994644658f * x * (5.0f * z2 - 1.0f);
    Y[14] = 1.445305721320277f  * z * (x2 - y2);
    Y[15] = 0.5900435899266435f * x * (x2 - 3.0f * y2);

    const uint4* __restrict__ Arow4 =
        (const uint4*)(g_Ah + (size_t)src * FANIN);
    uint4 v[8];
#pragma unroll
    for (int l = 0; l < 8; l++)
        v[l] = __ldg(&Arow4[l * 8 + el]);

    const int par = el >> 2;

    float acc[8];
#pragma unroll
    for (int i = 0; i < 8; i++) acc[i] = 0.f;

#pragma unroll
    for (int l = 0; l < 8; l++) {
        float yi = par ? Y[2 * l + 1] : Y[2 * l];
        float2 f0 = __half22float2(*(const __half2*)&v[l].x);
        float2 f1 = __half22float2(*(const __half2*)&v[l].y);
        float2 f2 = __half22float2(*(const __half2*)&v[l].z);
        float2 f3 = __half22float2(*(const __half2*)&v[l].w);
        acc[0] = fmaf(yi, f0.x, acc[0]); acc[1] = fmaf(yi, f0.y, acc[1]);
        acc[2] = fmaf(yi, f1.x, acc[2]); acc[3] = fmaf(yi, f1.y, acc[3]);
        acc[4] = fmaf(yi, f2.x, acc[4]); acc[5] = fmaf(yi, f2.y, acc[5]);
        acc[6] = fmaf(yi, f3.x, acc[6]); acc[7] = fmaf(yi, f3.y, acc[7]);
    }

#pragma unroll
    for (int i = 0; i < 8; i++)
        acc[i] += __shfl_xor_sync(gmask, acc[i], 4);

    float r0 = par ? acc[4] : acc[0];
    float r1 = par ? acc[5] : acc[1];
    float r2 = par ? acc[6] : acc[2];
    float r3 = par ? acc[7] : acc[3];

    float* dst = &out[(size_t)tgt * OUTC + (el & 3) * 8 + par * 4];
    asm volatile("red.global.add.v4.f32 [%0], {%1, %2, %3, %4};"
                 :: "l"(dst), "f"(r0), "f"(r1), "f"(r2), "f"(r3)
                 : "memory");
}

// ---------------------------------------------------------------------------
// Launcher
// Inputs (metadata order): node_features f32 [n_atoms,32], edge_vectors f32
// [n_edges,3], edge_index int32 [2,n_edges], W f32 [512,32], b f32 [32].
// Output: f32 [n_atoms, 32].
// ---------------------------------------------------------------------------
extern "C" void kernel_launch(void* const* d_in, const int* in_sizes, int n_in,
                              void* d_out, int out_size) {
    const float* nf  = (const float*)d_in[0];
    const float* ev  = (const float*)d_in[1];
    const int*   ei  = (const int*)d_in[2];
    const float* W   = (const float*)d_in[3];
    const float* b   = (const float*)d_in[4];
    float*       out = (float*)d_out;

    const int n_atoms = in_sizes[0] / HID;
    const int n_edges = in_sizes[1] / 3;

    // out = b (broadcast), float4
    {
        int n4 = out_size / 4;
        init_out_kernel<<<(n4 + 255) / 256, 256>>>((float4*)out, (const float4*)b, n4);
    }

    // A = NF @ W' via tensor cores (fp16 in, fp32 accum, fp16 out)
    {
        int grid = (n_atoms + PRE_BM - 1) / PRE_BM;
        precompute_mma_kernel<<<grid, 128>>>(nf, W, n_atoms);
    }

    // per-edge gather + scatter: 4 edges/warp, 32 edges/block
    {
        int grid = (n_edges + 31) / 32;
        edge_kernel<<<grid, 256>>>(ev, ei, out, n_edges, n_atoms);
    }
}